// round 7
// baseline (speedup 1.0000x reference)
#include <cuda_runtime.h>

// Attention decode: out[b,:] = softmax(q[b]·K[b]^T masked) · V[b]
// B=32, S=8192, D=512, fp32. HBM-bound: ~1.07 GB/launch.
// Fused split-K flash-decode, 2-stage K-prefetch software pipeline.

#define BB      32
#define SS      8192
#define DD      512
#define NSPLIT  8
#define ROWS_PER_BLOCK (SS / NSPLIT)    // 1024
#define NWARPS  4
#define NTHREADS (NWARPS * 32)          // 128
#define NBLK    (BB * NSPLIT)           // 256
#define NPAIRS  (ROWS_PER_BLOCK / 2)    // 512 row-pairs per CTA
#define WITER   (NPAIRS / NWARPS)       // 128 iterations per warp

// Split-K partials + fan-in counters (scratch; __device__ globals per rules)
__device__ float g_pm[NBLK];
__device__ float g_pl[NBLK];
__device__ float g_pacc[NBLK * DD];
__device__ int   g_cnt[BB] = {0};   // always returns to 0 by kernel end

// ---- load K row-pair (2 rows x 4 float4/lane) + mask pair for pair-index tt ----
#define LOADK(KB, M0v, M1v, tt) do {                                          \
    const int _r0 = row_base + 2 * (tt);                                      \
    const float4* _k0 = kb + (size_t)_r0 * (DD / 4);                          \
    M0v = __ldg(&mb[_r0]);                                                    \
    M1v = __ldg(&mb[_r0 + 1]);                                                \
    _Pragma("unroll")                                                         \
    for (int _j = 0; _j < 4; _j++) {                                          \
        KB[_j]     = __ldcs(&_k0[ln + 32 * _j]);                              \
        KB[4 + _j] = __ldcs(&_k0[(DD / 4) + ln + 32 * _j]);                   \
    }                                                                         \
} while (0)

// ---- issue V loads for pair tt (into va/vc), no dependence on K data ----
#define LOADV(tt) do {                                                        \
    const int _r0 = row_base + 2 * (tt);                                      \
    const float4* _v0 = vb + (size_t)_r0 * (DD / 4);                          \
    _Pragma("unroll")                                                         \
    for (int _j = 0; _j < 4; _j++) {                                          \
        va[_j] = __ldcs(&_v0[ln + 32 * _j]);                                  \
        vc[_j] = __ldcs(&_v0[(DD / 4) + ln + 32 * _j]);                       \
    }                                                                         \
} while (0)

// ---- scores + online softmax + V accumulate, consuming KB and va/vc ----
#define MATH(KB, M0v, M1v) do {                                               \
    float d0 = 0.f, d1 = 0.f;                                                 \
    _Pragma("unroll")                                                         \
    for (int _j = 0; _j < 4; _j++) {                                          \
        d0 = fmaf(qf[_j].x, KB[_j].x, d0);                                    \
        d0 = fmaf(qf[_j].y, KB[_j].y, d0);                                    \
        d0 = fmaf(qf[_j].z, KB[_j].z, d0);                                    \
        d0 = fmaf(qf[_j].w, KB[_j].w, d0);                                    \
        d1 = fmaf(qf[_j].x, KB[4 + _j].x, d1);                                \
        d1 = fmaf(qf[_j].y, KB[4 + _j].y, d1);                                \
        d1 = fmaf(qf[_j].z, KB[4 + _j].z, d1);                                \
        d1 = fmaf(qf[_j].w, KB[4 + _j].w, d1);                                \
    }                                                                         \
    _Pragma("unroll")                                                         \
    for (int _o = 16; _o > 0; _o >>= 1) {                                     \
        d0 += __shfl_xor_sync(0xffffffffu, d0, _o);                           \
        d1 += __shfl_xor_sync(0xffffffffu, d1, _o);                           \
    }                                                                         \
    const float s0 = (M0v != 0) ? d0 : -1e9f;                                 \
    const float s1 = (M1v != 0) ? d1 : -1e9f;                                 \
    const float mn = fmaxf(m, fmaxf(s0, s1));                                 \
    if (mn > m) {                                                             \
        const float corr = __expf(m - mn);                                    \
        l *= corr;                                                            \
        _Pragma("unroll")                                                     \
        for (int _j = 0; _j < 4; _j++) {                                      \
            acc[_j].x *= corr; acc[_j].y *= corr;                             \
            acc[_j].z *= corr; acc[_j].w *= corr;                             \
        }                                                                     \
        m = mn;                                                               \
    }                                                                         \
    const float p0 = __expf(s0 - m);                                          \
    const float p1 = __expf(s1 - m);                                          \
    l += p0 + p1;                                                             \
    _Pragma("unroll")                                                         \
    for (int _j = 0; _j < 4; _j++) {                                          \
        acc[_j].x = fmaf(p0, va[_j].x, fmaf(p1, vc[_j].x, acc[_j].x));        \
        acc[_j].y = fmaf(p0, va[_j].y, fmaf(p1, vc[_j].y, acc[_j].y));        \
        acc[_j].z = fmaf(p0, va[_j].z, fmaf(p1, vc[_j].z, acc[_j].z));        \
        acc[_j].w = fmaf(p0, va[_j].w, fmaf(p1, vc[_j].w, acc[_j].w));        \
    }                                                                         \
} while (0)

__global__ __launch_bounds__(NTHREADS, 3)
void attn_fused(const float* __restrict__ q,
                const float* __restrict__ k,
                const float* __restrict__ v,
                const int*   __restrict__ mask,
                float* __restrict__ out)
{
    __shared__ float s_m[NWARPS];
    __shared__ float s_l[NWARPS];
    __shared__ float s_acc[DD];
    __shared__ int   s_last;

    const int b     = blockIdx.x / NSPLIT;
    const int split = blockIdx.x % NSPLIT;
    const int w     = threadIdx.x >> 5;
    const int ln    = threadIdx.x & 31;

    for (int i = threadIdx.x; i < DD; i += NTHREADS) s_acc[i] = 0.0f;

    // q fragment: lane ln holds dims {4*(ln+32*j) + c}
    const float4* q4 = (const float4*)(q + (size_t)b * DD);
    float4 qf[4];
#pragma unroll
    for (int j = 0; j < 4; j++) qf[j] = q4[ln + 32 * j];

    const float4* kb = (const float4*)(k + (size_t)b * SS * DD);
    const float4* vb = (const float4*)(v + (size_t)b * SS * DD);
    const int*    mb = mask + (size_t)b * SS;

    float  m = -1e30f;
    float  l = 0.0f;
    float4 acc[4];
#pragma unroll
    for (int j = 0; j < 4; j++) acc[j] = make_float4(0.f, 0.f, 0.f, 0.f);

    const int row_base = split * ROWS_PER_BLOCK;

    // -------- 2-stage pipelined stream over WITER=128 row-pairs --------
    float4 K0[8], K1[8], va[4], vc[4];
    int    m00, m01, m10, m11;

    int t = w;                       // pair index, stride NWARPS
    LOADK(K0, m00, m01, t);          // prologue

    for (int i = 0; i < (WITER - 2) / 2; i++) {   // 63 double-steps
        // step A: consume K0/pair t, prefetch K1/pair t+NWARPS
        LOADV(t);
        LOADK(K1, m10, m11, t + NWARPS);
        MATH(K0, m00, m01);
        t += NWARPS;
        // step B: consume K1, prefetch K0
        LOADV(t);
        LOADK(K0, m00, m01, t + NWARPS);
        MATH(K1, m10, m11);
        t += NWARPS;
    }
    // final step A: prefetch last pair
    LOADV(t);
    LOADK(K1, m10, m11, t + NWARPS);
    MATH(K0, m00, m01);
    t += NWARPS;
    // final step B: no prefetch
    LOADV(t);
    MATH(K1, m10, m11);

    // -------- combine warps within block --------
    if (ln == 0) { s_m[w] = m; s_l[w] = l; }
    __syncthreads();
    const float M = fmaxf(fmaxf(s_m[0], s_m[1]), fmaxf(s_m[2], s_m[3]));
    const float scale = __expf(m - M);
#pragma unroll
    for (int j = 0; j < 4; j++) {
        const int d = 4 * (ln + 32 * j);
        atomicAdd(&s_acc[d + 0], scale * acc[j].x);
        atomicAdd(&s_acc[d + 1], scale * acc[j].y);
        atomicAdd(&s_acc[d + 2], scale * acc[j].z);
        atomicAdd(&s_acc[d + 3], scale * acc[j].w);
    }
    __syncthreads();

    // -------- write partials --------
    const int pidx = blockIdx.x;
    if (threadIdx.x == 0) {
        float L = 0.f;
#pragma unroll
        for (int i = 0; i < NWARPS; i++) L += s_l[i] * __expf(s_m[i] - M);
        g_pm[pidx] = M;
        g_pl[pidx] = L;
    }
    for (int i = threadIdx.x; i < DD; i += NTHREADS)
        g_pacc[(size_t)pidx * DD + i] = s_acc[i];

    // -------- fan-in: last CTA of this batch reduces the splits --------
    __threadfence();
    __syncthreads();
    if (threadIdx.x == 0)
        s_last = (atomicAdd(&g_cnt[b], 1) == NSPLIT - 1) ? 1 : 0;
    __syncthreads();
    if (!s_last) return;

    float Mg = -1e30f;
#pragma unroll
    for (int i = 0; i < NSPLIT; i++) Mg = fmaxf(Mg, g_pm[b * NSPLIT + i]);
    float wgt[NSPLIT];
    float Lg = 0.f;
#pragma unroll
    for (int i = 0; i < NSPLIT; i++) {
        wgt[i] = __expf(g_pm[b * NSPLIT + i] - Mg);
        Lg += g_pl[b * NSPLIT + i] * wgt[i];
    }
    const float invL = 1.0f / Lg;

    for (int d = threadIdx.x; d < DD; d += NTHREADS) {
        float a = 0.f;
#pragma unroll
        for (int i = 0; i < NSPLIT; i++)
            a += wgt[i] * g_pacc[(size_t)(b * NSPLIT + i) * DD + d];
        out[(size_t)b * DD + d] = a * invL;
    }

    // reset counter for next graph replay (deterministic: ends at 0)
    if (threadIdx.x == 0) g_cnt[b] = 0;
}

extern "C" void kernel_launch(void* const* d_in, const int* in_sizes, int n_in,
                              void* d_out, int out_size)
{
    const float* q    = (const float*)d_in[0];   // [32, 512]
    const float* k    = (const float*)d_in[1];   // [32, 8192, 512]
    const float* v    = (const float*)d_in[2];   // [32, 8192, 512]
    const int*   mask = (const int*)  d_in[3];   // [32, 1, 8192]
    float* out = (float*)d_out;                  // [32, 512]

    attn_fused<<<NBLK, NTHREADS>>>(q, k, v, mask, out);
}

// round 9
// speedup vs baseline: 1.0374x; 1.0374x over previous
#include <cuda_runtime.h>

// Attention decode: out[b,:] = softmax(q[b]·K[b]^T masked) · V[b]
// B=32, S=8192, D=512, fp32. HBM-bound: ~1.07 GB/launch.
// Fused split-K flash-decode + per-batch DYNAMIC warp-level work stealing
// (kills the CTA drain-tail that left ~14% of DRAM cycles idle).

#define BB      32
#define SS      8192
#define DD      512
#define CTAS_PER_B 16
#define NWARPS  4
#define NTHREADS (NWARPS * 32)          // 128
#define NBLK    (BB * CTAS_PER_B)       // 512
#define UNIT_ROWS 4                     // rows per dynamic grab (2 pair-iters)
#define UNITS_PER_B (SS / UNIT_ROWS)    // 2048

// Split-K partials + counters (scratch; __device__ globals per rules).
// All counters return to 0 by kernel end (graph-replay clean).
__device__ float g_pm[NBLK];
__device__ float g_pl[NBLK];
__device__ float g_pacc[NBLK * DD];
__device__ int   g_cnt[BB];
__device__ int   g_tile[BB * 32];       // padded: one counter per 128 B

__global__ __launch_bounds__(NTHREADS, 4)
void attn_fused(const float* __restrict__ q,
                const float* __restrict__ k,
                const float* __restrict__ v,
                const int*   __restrict__ mask,
                float* __restrict__ out)
{
    __shared__ float s_m[NWARPS];
    __shared__ float s_l[NWARPS];
    __shared__ float s_acc[DD];
    __shared__ int   s_last;

    const int b  = blockIdx.x / CTAS_PER_B;
    const int w  = threadIdx.x >> 5;
    const int ln = threadIdx.x & 31;

    for (int i = threadIdx.x; i < DD; i += NTHREADS) s_acc[i] = 0.0f;

    // q fragment: lane ln holds dims {4*(ln+32*j) + c}, j=0..3, c=0..3
    const float4* q4 = (const float4*)(q + (size_t)b * DD);
    float4 qf[4];
#pragma unroll
    for (int j = 0; j < 4; j++) qf[j] = q4[ln + 32 * j];

    const float4* kb = (const float4*)(k + (size_t)b * SS * DD);
    const float4* vb = (const float4*)(v + (size_t)b * SS * DD);
    const int*    mb = mask + (size_t)b * SS;
    int* const    tile_ctr = &g_tile[b * 32];

    float  m = -1e30f;
    float  l = 0.0f;
    float4 acc[4];
#pragma unroll
    for (int j = 0; j < 4; j++) acc[j] = make_float4(0.f, 0.f, 0.f, 0.f);

    // -------- dynamic unit loop: warp grabs 4-row units, prefetch next grab ----
    int u = (ln == 0) ? atomicAdd(tile_ctr, 1) : 0;
    u = __shfl_sync(0xffffffffu, u, 0);

    while (u < UNITS_PER_B) {
        int unext = (ln == 0) ? atomicAdd(tile_ctr, 1) : 0;   // in flight under math

        const int r_base = u * UNIT_ROWS;
#pragma unroll
        for (int pp = 0; pp < 2; pp++) {
            const int r0 = r_base + 2 * pp;
            const int r1 = r0 + 1;
            const float4* k0 = kb + (size_t)r0 * (DD / 4);
            const float4* k1 = kb + (size_t)r1 * (DD / 4);
            const float4* v0 = vb + (size_t)r0 * (DD / 4);
            const float4* v1 = vb + (size_t)r1 * (DD / 4);

            // issue mask + all 16 streaming loads up front: 8 KB in flight
            const int m0 = __ldg(&mb[r0]);
            const int m1 = __ldg(&mb[r1]);
            float4 ka[4], kc[4], va[4], vc[4];
#pragma unroll
            for (int j = 0; j < 4; j++) {
                ka[j] = __ldcs(&k0[ln + 32 * j]);
                kc[j] = __ldcs(&k1[ln + 32 * j]);
                va[j] = __ldcs(&v0[ln + 32 * j]);
                vc[j] = __ldcs(&v1[ln + 32 * j]);
            }

            float d0 = 0.f, d1 = 0.f;
#pragma unroll
            for (int j = 0; j < 4; j++) {
                d0 = fmaf(qf[j].x, ka[j].x, d0); d0 = fmaf(qf[j].y, ka[j].y, d0);
                d0 = fmaf(qf[j].z, ka[j].z, d0); d0 = fmaf(qf[j].w, ka[j].w, d0);
                d1 = fmaf(qf[j].x, kc[j].x, d1); d1 = fmaf(qf[j].y, kc[j].y, d1);
                d1 = fmaf(qf[j].z, kc[j].z, d1); d1 = fmaf(qf[j].w, kc[j].w, d1);
            }
#pragma unroll
            for (int o = 16; o > 0; o >>= 1) {
                d0 += __shfl_xor_sync(0xffffffffu, d0, o);
                d1 += __shfl_xor_sync(0xffffffffu, d1, o);
            }

            const float s0 = (m0 != 0) ? d0 : -1e9f;
            const float s1 = (m1 != 0) ? d1 : -1e9f;

            const float mn = fmaxf(m, fmaxf(s0, s1));
            if (mn > m) {  // warp-uniform, rare after warmup
                const float corr = __expf(m - mn);
                l *= corr;
#pragma unroll
                for (int j = 0; j < 4; j++) {
                    acc[j].x *= corr; acc[j].y *= corr;
                    acc[j].z *= corr; acc[j].w *= corr;
                }
                m = mn;
            }
            const float p0 = __expf(s0 - m);
            const float p1 = __expf(s1 - m);
            l += p0 + p1;
#pragma unroll
            for (int j = 0; j < 4; j++) {
                acc[j].x = fmaf(p0, va[j].x, fmaf(p1, vc[j].x, acc[j].x));
                acc[j].y = fmaf(p0, va[j].y, fmaf(p1, vc[j].y, acc[j].y));
                acc[j].z = fmaf(p0, va[j].z, fmaf(p1, vc[j].z, acc[j].z));
                acc[j].w = fmaf(p0, va[j].w, fmaf(p1, vc[j].w, acc[j].w));
            }
        }

        u = __shfl_sync(0xffffffffu, unext, 0);
    }

    // -------- combine warps within block --------
    if (ln == 0) { s_m[w] = m; s_l[w] = l; }
    __syncthreads();
    const float M = fmaxf(fmaxf(s_m[0], s_m[1]), fmaxf(s_m[2], s_m[3]));
    const float scale = (l > 0.f) ? __expf(m - M) : 0.f;
#pragma unroll
    for (int j = 0; j < 4; j++) {
        const int d = 4 * (ln + 32 * j);
        atomicAdd(&s_acc[d + 0], scale * acc[j].x);
        atomicAdd(&s_acc[d + 1], scale * acc[j].y);
        atomicAdd(&s_acc[d + 2], scale * acc[j].z);
        atomicAdd(&s_acc[d + 3], scale * acc[j].w);
    }
    __syncthreads();

    // -------- write partials --------
    const int pidx = blockIdx.x;
    if (threadIdx.x == 0) {
        float L = 0.f;
#pragma unroll
        for (int i = 0; i < NWARPS; i++) L += s_l[i] * __expf(s_m[i] - M);
        g_pm[pidx] = M;
        g_pl[pidx] = L;
    }
    for (int i = threadIdx.x; i < DD; i += NTHREADS)
        g_pacc[(size_t)pidx * DD + i] = s_acc[i];

    // -------- fan-in: last CTA of this batch reduces the partials --------
    __threadfence();
    __syncthreads();
    if (threadIdx.x == 0)
        s_last = (atomicAdd(&g_cnt[b], 1) == CTAS_PER_B - 1) ? 1 : 0;
    __syncthreads();
    if (!s_last) return;

    float Mg = -1e30f;
#pragma unroll
    for (int i = 0; i < CTAS_PER_B; i++) Mg = fmaxf(Mg, g_pm[b * CTAS_PER_B + i]);
    float wgt[CTAS_PER_B];
    float Lg = 0.f;
#pragma unroll
    for (int i = 0; i < CTAS_PER_B; i++) {
        wgt[i] = __expf(g_pm[b * CTAS_PER_B + i] - Mg);
        Lg += g_pl[b * CTAS_PER_B + i] * wgt[i];
    }
    const float invL = 1.0f / Lg;

    for (int d = threadIdx.x; d < DD; d += NTHREADS) {
        float a = 0.f;
#pragma unroll
        for (int i = 0; i < CTAS_PER_B; i++)
            a += wgt[i] * g_pacc[(size_t)(b * CTAS_PER_B + i) * DD + d];
        out[(size_t)b * DD + d] = a * invL;
    }

    // reset counters for next graph replay (deterministic: end at 0)
    if (threadIdx.x == 0) {
        g_cnt[b] = 0;
        g_tile[b * 32] = 0;
    }
}

extern "C" void kernel_launch(void* const* d_in, const int* in_sizes, int n_in,
                              void* d_out, int out_size)
{
    const float* q    = (const float*)d_in[0];   // [32, 512]
    const float* k    = (const float*)d_in[1];   // [32, 8192, 512]
    const float* v    = (const float*)d_in[2];   // [32, 8192, 512]
    const int*   mask = (const int*)  d_in[3];   // [32, 1, 8192]
    float* out = (float*)d_out;                  // [32, 512]

    attn_fused<<<NBLK, NTHREADS>>>(q, k, v, mask, out);
}